// round 13
// baseline (speedup 1.0000x reference)
#include <cuda_runtime.h>
#include <cuda_bf16.h>
#include <math.h>
#include <stdint.h>

// ---------------------------------------------------------------------------
// PointNet++ encoder: 3 SA layers. B=8, N=4096.
// L1: m=2048 r=0.2 (3->32->32). L2: m=512 r=0.4 (32->64->64).
// L3: m=512 r=1.0 (64->128->128). k=64.
// Output = concat(x3 [8,512,128], p3 [8,512,3], batch [8,512]) as f32.
//
// R6 structure (best proven). FPS argmax: value-only FMNMX tree + keys-only
// block combine; index resolved lazily by the winning warp(s) via equality
// scan + reduce_min + atomicMin (exact first-index tie-break preserved).
//
// Launch plan:
//   1. fps1 (256 thr)
//   2. combo2: fps2 | ballq1
//   3. combo3: fps3 | mlp1(+fuse xw2) | ballq2
//   4. combo4: mlp2(+fuse xw3) | ballq3 | pack
//   5. mlp3 -> out
// ---------------------------------------------------------------------------

#define BB   8
#define N1   4096
#define M1   2048
#define M2   512
#define M3   512
#define KNBR 64
#define TPB  256

typedef unsigned long long ull;

// ------------------------------ scratch ------------------------------------
__device__ __align__(16) float g_p1[BB * M1 * 3];
__device__ __align__(16) float g_p2[BB * M2 * 3];
__device__ __align__(16) float g_p3[BB * M3 * 3];
__device__ __align__(16) float g_xw2[BB * M1 * 64];    // b21 + x1 @ w21[:32]
__device__ __align__(16) float g_xw3[BB * M2 * 128];   // b31 + x2 @ w31[:64]
__device__ int   g_nbr1[BB * M1 * KNBR];
__device__ int   g_cnt1[BB * M1];
__device__ int   g_nbr2[BB * M2 * KNBR];
__device__ int   g_cnt2[BB * M2];
__device__ int   g_nbr3[BB * M3 * KNBR];
__device__ int   g_cnt3[BB * M3];

// ------------------------------ f32x2 packed helpers ------------------------
__device__ __forceinline__ ull pk2(float lo, float hi) {
    ull r; asm("mov.b64 %0, {%1, %2};" : "=l"(r) : "f"(lo), "f"(hi)); return r;
}
__device__ __forceinline__ void upk2(float& lo, float& hi, ull v) {
    asm("mov.b64 {%0, %1}, %2;" : "=f"(lo), "=f"(hi) : "l"(v));
}
__device__ __forceinline__ ull add2(ull a, ull b) {
    ull d; asm("add.rn.f32x2 %0, %1, %2;" : "=l"(d) : "l"(a), "l"(b)); return d;
}
__device__ __forceinline__ ull mul2(ull a, ull b) {
    ull d; asm("mul.rn.f32x2 %0, %1, %2;" : "=l"(d) : "l"(a), "l"(b)); return d;
}
__device__ __forceinline__ ull fma2(ull a, ull b, ull c) {
    ull d; asm("fma.rn.f32x2 %0, %1, %2, %3;" : "=l"(d) : "l"(a), "l"(b), "l"(c)); return d;
}

// ------------------------------ FPS ----------------------------------------
// Packed f32x2 distance update (bit-exact). Value-only argmax (FMNMX tree,
// REDUX max, keys-only combine); winning warp(s) resolve the first index
// attaining the max via equality scan + reduce_min + atomicMin. Two barriers
// per step; winner slots parity-double-buffered.
template <int N, int M, int THREADS>
__device__ __forceinline__ void fps_impl(const float* __restrict__ pb,
                                         float* __restrict__ po) {
    constexpr int P  = N / THREADS;
    constexpr int H  = P / 2;
    constexpr int NW = THREADS / 32;
    extern __shared__ char smraw[];
    float*    sx  = (float*)smraw;
    float*    sy  = sx + N;
    float*    sz  = sy + N;
    unsigned* kb  = (unsigned*)(sz + N);   // [2][NW] key slots
    int*      wsl = (int*)(kb + 2 * NW);   // [2] winner index slots

    const int t = threadIdx.x;
    const int lane = t & 31, wid = t >> 5;

    for (int i = t; i < N; i += THREADS) {
        sx[i] = pb[3 * i + 0];
        sy[i] = pb[3 * i + 1];
        sz[i] = pb[3 * i + 2];
    }
    __syncthreads();

    ull rxp[H], ryp[H], rzp[H];
    float md[P];
    const float x0 = sx[0], y0 = sy[0], z0 = sz[0];
    {
        const ull ncx = pk2(-x0, -x0), ncy = pk2(-y0, -y0), ncz = pk2(-z0, -z0);
#pragma unroll
        for (int h = 0; h < H; h++) {
            int i0 = t + (2 * h) * THREADS, i1 = t + (2 * h + 1) * THREADS;
            rxp[h] = pk2(sx[i0], sx[i1]);
            ryp[h] = pk2(sy[i0], sy[i1]);
            rzp[h] = pk2(sz[i0], sz[i1]);
            ull dx = add2(rxp[h], ncx);
            ull dy = add2(ryp[h], ncy);
            ull dz = add2(rzp[h], ncz);
            ull d2 = fma2(dz, dz, fma2(dy, dy, mul2(dx, dx)));
            upk2(md[2 * h], md[2 * h + 1], d2);
        }
    }
    if (t == 0) { po[0] = x0; po[1] = y0; po[2] = z0; }

    for (int s = 1; s < M; s++) {
        // value-only max tree (md >= 0 -> float bits monotone as unsigned)
        float tv[P];
#pragma unroll
        for (int j = 0; j < P; j++) tv[j] = md[j];
#pragma unroll
        for (int st = 1; st < P; st <<= 1)
#pragma unroll
            for (int j = 0; j + st < P; j += 2 * st)
                tv[j] = fmaxf(tv[j], tv[j + st]);
        const float bv = tv[0];
        const unsigned key  = __float_as_uint(bv);
        const unsigned wmax = __reduce_max_sync(0xffffffffu, key);
        const int par = (s & 1);
        if (lane == 0) kb[par * NW + wid] = wmax;
        if (t == 0) wsl[par] = 0x7fffffff;
        __syncthreads();
        // keys-only block combine
        unsigned bk = kb[par * NW];
#pragma unroll
        for (int w2 = 1; w2 < NW; w2++) bk = max(bk, kb[par * NW + w2]);
        // lazy index resolution: only warps holding the block max participate
        if (wmax == bk) {
            int cand = 0x7fffffff;
            if (key == bk) {
#pragma unroll
                for (int j = 0; j < P; j++)
                    if (md[j] == bv) cand = min(cand, t + j * THREADS);
            }
            int wmin = __reduce_min_sync(0xffffffffu, cand);
            if (lane == 0) atomicMin(&wsl[par], wmin);
        }
        __syncthreads();
        const int bx = wsl[par];

        const float cx = sx[bx], cy = sy[bx], cz = sz[bx];
        if (t == 0) { po[3 * s] = cx; po[3 * s + 1] = cy; po[3 * s + 2] = cz; }
        const ull ncx = pk2(-cx, -cx), ncy = pk2(-cy, -cy), ncz = pk2(-cz, -cz);
#pragma unroll
        for (int h = 0; h < H; h++) {
            ull dx = add2(rxp[h], ncx);
            ull dy = add2(ryp[h], ncy);
            ull dz = add2(rzp[h], ncz);
            ull d2 = fma2(dz, dz, fma2(dy, dy, mul2(dx, dx)));
            float d0, d1; upk2(d0, d1, d2);
            md[2 * h]     = fminf(md[2 * h], d0);
            md[2 * h + 1] = fminf(md[2 * h + 1], d1);
        }
    }
}

static __host__ __device__ constexpr size_t fps_bytes(int N, int THREADS) {
    return (size_t)(3 * N) * 4 + 2 * (THREADS / 32) * 4 + 2 * 4;
}

// ------------------------------ ball query (R6 proven) -----------------------
template <int NSRC, int THREADS>
__device__ __forceinline__ void ballq_impl(int q, const float* __restrict__ pos_src,
                                           const float* __restrict__ pos_q,
                                           int* __restrict__ nbr, int* __restrict__ cnt,
                                           float rsq, int Mq) {
    extern __shared__ char smraw[];
    unsigned* s_keys = (unsigned*)smraw;
    int* s_idx  = (int*)(s_keys + NSRC);
    int* hist   = s_idx + NSRC;          // 256
    int* s_scal = hist + 256;            // [0]=counter [1]=prefix [2]=need [3]=outcnt

    const int b = q / Mq;
    const int t = threadIdx.x;
    if (t == 0) { s_scal[0] = 0; s_scal[3] = 0; }
    __syncthreads();

    const float qx = pos_q[q * 3 + 0];
    const float qy = pos_q[q * 3 + 1];
    const float qz = pos_q[q * 3 + 2];
    const float qn = fmaf(qz, qz, fmaf(qy, qy, qx * qx));
    const float* ps = pos_src + (size_t)b * NSRC * 3;

    for (int i = t; i < NSRC; i += THREADS) {
        float sxx = ps[i * 3 + 0], syy = ps[i * 3 + 1], szz = ps[i * 3 + 2];
        float sn  = fmaf(szz, szz, fmaf(syy, syy, sxx * sxx));
        float dot = fmaf(qz, szz, fmaf(qy, syy, qx * sxx));
        float d2  = fmaf(-2.0f, dot, qn + sn);
        if (d2 <= rsq) {
            int p = atomicAdd(&s_scal[0], 1);
            unsigned u = __float_as_uint(d2);
            u = ((int)u >= 0) ? (u ^ 0x80000000u) : ~u;   // monotone f32->u32
            s_keys[p] = u;
            s_idx[p]  = i;
        }
    }
    __syncthreads();
    const int c = s_scal[0];
    int* onbr = nbr + (size_t)q * KNBR;

    if (c <= KNBR) {
        for (int e = t; e < c; e += THREADS) onbr[e] = s_idx[e];
        if (t == 0) cnt[q] = c;
        return;
    }

    unsigned prefix = 0;
    int need = KNBR;
#pragma unroll
    for (int byte = 3; byte >= 0; byte--) {
        for (int i = t; i < 256; i += THREADS) hist[i] = 0;
        __syncthreads();
        const int sh = byte * 8;
        const unsigned himask = (byte == 3) ? 0u : (0xFFFFFFFFu << (sh + 8));
        for (int e = t; e < c; e += THREADS) {
            unsigned k = s_keys[e];
            if ((k & himask) == prefix) atomicAdd(&hist[(k >> sh) & 255], 1);
        }
        __syncthreads();
        if (t < 32) {
            int loc[8], ssum = 0;
#pragma unroll
            for (int j = 0; j < 8; j++) { loc[j] = hist[t * 8 + j]; ssum += loc[j]; }
            int inc = ssum;
#pragma unroll
            for (int off = 1; off < 32; off <<= 1) {
                int n = __shfl_up_sync(0xffffffffu, inc, off);
                if (t >= off) inc += n;
            }
            int excl = inc - ssum;
            if (need > excl && need <= inc) {
                int cum = excl;
#pragma unroll
                for (int j = 0; j < 8; j++) {
                    cum += loc[j];
                    if (need <= cum) {
                        s_scal[1] = (int)(prefix | ((unsigned)(t * 8 + j) << sh));
                        s_scal[2] = need - (cum - loc[j]);
                        break;
                    }
                }
            }
        }
        __syncthreads();
        prefix = (unsigned)s_scal[1];
        need   = s_scal[2];
    }

    for (int e = t; e < c; e += THREADS) {
        unsigned k = s_keys[e];
        if (k < prefix) {
            int p = atomicAdd(&s_scal[3], 1);
            onbr[p] = s_idx[e];
        } else if (k == prefix) {
            int my = s_idx[e];
            int r = 0;
            for (int j = 0; j < c; j++)
                r += (s_keys[j] == prefix) && (s_idx[j] < my);
            if (r < need) onbr[KNBR - need + r] = my;
        }
    }
    if (t == 0) cnt[q] = KNBR;
}

static __host__ __device__ constexpr size_t ballq_bytes(int NSRC) {
    return (size_t)NSRC * 8 + 256 * 4 + 16;
}

// ------------------------------ MLP helpers ---------------------------------
template <int V>
__device__ __forceinline__ void vldf(float* d, const float* s) {
    if constexpr (V == 4) { float4 v = *(const float4*)s; d[0]=v.x; d[1]=v.y; d[2]=v.z; d[3]=v.w; }
    else if constexpr (V == 2) { float2 v = *(const float2*)s; d[0]=v.x; d[1]=v.y; }
    else { d[0] = s[0]; }
}
template <int V>
__device__ __forceinline__ void vstf(float* d, const float* s) {
    if constexpr (V == 4) { *(float4*)d = make_float4(s[0], s[1], s[2], s[3]); }
    else if constexpr (V == 2) { *(float2*)d = make_float2(s[0], s[1]); }
    else { d[0] = s[0]; }
}
template <int V>
__device__ __forceinline__ void vldg(float* d, const float* s) {
    if constexpr (V == 4) { float4 v = __ldg((const float4*)s); d[0]=v.x; d[1]=v.y; d[2]=v.z; d[3]=v.w; }
    else if constexpr (V == 2) { float2 v = __ldg((const float2*)s); d[0]=v.x; d[1]=v.y; }
    else { d[0] = __ldg(s); }
}

// ------------------------------ MLP layer 1 (msg-based) + fuse xw2 ----------
template <int NB, int THREADS, int CNEXT>
__device__ __forceinline__ void mlp1_impl(int qblk,
        const float* __restrict__ pos_src, const float* __restrict__ pos_q,
        const int* __restrict__ nbr, const int* __restrict__ cnt,
        const float* __restrict__ w1, const float* __restrict__ b1,
        const float* __restrict__ w2, const float* __restrict__ b2,
        const float* __restrict__ wn, const float* __restrict__ bn,
        float* __restrict__ xw_out, int NSRC, int Mq) {
    constexpr int CMID = 32, COUT = 32, MSG = 6;
    constexpr int WPB = THREADS / 32;

    extern __shared__ char smraw[];
    float* sw1  = (float*)smraw;             // 6*32
    float* sb1  = sw1 + MSG * CMID;          // 32
    float* sw2  = sb1 + CMID;                // 32*32
    float* sb2  = sw2 + CMID * COUT;         // 32
    float* smsg = sb2 + COUT;                // WPB*NB*6
    float* sh1  = smsg + WPB * NB * MSG;     // WPB*NB*32
    float* srow = sh1 + WPB * NB * CMID;     // WPB*32

    const int t = threadIdx.x;
    for (int i = t; i < MSG * CMID; i += THREADS) sw1[i] = w1[i];
    for (int i = t; i < CMID; i += THREADS) sb1[i] = b1[i];
    for (int i = t; i < CMID * COUT; i += THREADS) sw2[i] = w2[i];
    for (int i = t; i < COUT; i += THREADS) sb2[i] = b2[i];
    __syncthreads();

    const int w = t >> 5, lane = t & 31;
    const int q = qblk * WPB + w;
    const int b = q / Mq;
    const int kcnt = cnt[q];
    const float qx = pos_q[q * 3 + 0];
    const float qy = pos_q[q * 3 + 1];
    const float qz = pos_q[q * 3 + 2];
    float* msg = smsg + w * NB * MSG;
    float* h1  = sh1 + w * NB * CMID;
    const int* nb_ptr = nbr + (size_t)q * KNBR;
    const float* ps = pos_src + (size_t)b * NSRC * 3;

    const float bias1 = sb1[lane];
    const float bias2 = sb2[lane];
    float vmax = -INFINITY;

    for (int n0 = 0; n0 < kcnt; n0 += NB) {
        const int nv = min(NB, kcnt - n0);
        for (int e = lane; e < NB * MSG; e += 32) {
            int nbn = e / MSG, i = e - nbn * MSG;
            float v = 0.0f;
            if (nbn < nv) {
                int nid = nb_ptr[n0 + nbn];
                if (i < 3) {
                    v = ps[nid * 3 + i];
                } else {
                    float qc = (i == 3) ? qx : ((i == 4) ? qy : qz);
                    v = ps[nid * 3 + (i - 3)] - qc;
                }
            }
            msg[e] = v;
        }
        __syncwarp();
        float acc[NB];
#pragma unroll
        for (int nbn = 0; nbn < NB; nbn++) acc[nbn] = bias1;
#pragma unroll
        for (int i = 0; i < MSG; i++) {
            float wv = sw1[i * CMID + lane];
#pragma unroll
            for (int nbn = 0; nbn < NB; nbn++)
                acc[nbn] = fmaf(msg[nbn * MSG + i], wv, acc[nbn]);
        }
#pragma unroll
        for (int nbn = 0; nbn < NB; nbn++)
            h1[nbn * CMID + lane] = fmaxf(acc[nbn], 0.0f);
        __syncwarp();
        float acc2[NB];
#pragma unroll
        for (int nbn = 0; nbn < NB; nbn++) acc2[nbn] = bias2;
        for (int j = 0; j < CMID; j += 2) {
            float wv0 = sw2[j * COUT + lane];
            float wv1 = sw2[(j + 1) * COUT + lane];
#pragma unroll
            for (int nbn = 0; nbn < NB; nbn++) {
                float2 hp = *(const float2*)(h1 + nbn * CMID + j);
                acc2[nbn] = fmaf(hp.x, wv0, acc2[nbn]);
                acc2[nbn] = fmaf(hp.y, wv1, acc2[nbn]);
            }
        }
#pragma unroll
        for (int nbn = 0; nbn < NB; nbn++)
            if (nbn < nv) vmax = fmaxf(vmax, acc2[nbn]);
        __syncwarp();
    }
    const float ov = (kcnt > 0) ? vmax : 0.0f;
    srow[w * COUT + lane] = ov;
    __syncwarp();
    const float* row = srow + w * COUT;
#pragma unroll
    for (int o = lane; o < CNEXT; o += 32) {
        float a = __ldg(&bn[o]);
#pragma unroll 8
        for (int c = 0; c < COUT; c++)
            a = fmaf(row[c], __ldg(&wn[c * CNEXT + o]), a);
        xw_out[(size_t)q * CNEXT + o] = a;
    }
}

static __host__ __device__ constexpr size_t mlp1_bytes(int NB, int THREADS) {
    int WPB = THREADS / 32;
    return (size_t)(6 * 32 + 32 + 32 * 32 + 32 + WPB * NB * 6 +
                    WPB * NB * 32 + WPB * 32) * 4;
}

// ------------------------------ MLP layers 2/3 (xw-based) -------------------
template <int CMID, int COUT, int NB, int THREADS, int CNEXT>
__device__ __forceinline__ void mlpxw_impl(int qblk,
        const float* __restrict__ xw_src, const float* __restrict__ pos_src,
        const float* __restrict__ pos_q, const int* __restrict__ nbr,
        const int* __restrict__ cnt,
        const float* __restrict__ w1pos,      // [3][CMID]
        const float* __restrict__ w2, const float* __restrict__ b2,
        const float* __restrict__ wn, const float* __restrict__ bn,
        float* __restrict__ dst, int NSRC, int Mq) {
    constexpr int V1  = CMID / 32;
    constexpr int V2  = COUT / 32;
    constexpr int WPB = THREADS / 32;

    extern __shared__ char smraw[];
    float* sw1p = (float*)smraw;             // 3*CMID
    float* sw2  = sw1p + 3 * CMID;           // CMID*COUT
    float* sb2  = sw2 + CMID * COUT;         // COUT
    float* smsg = sb2 + COUT;                // WPB*NB*3
    float* sh1  = smsg + WPB * NB * 3;       // WPB*NB*CMID
    float* srow = sh1 + WPB * NB * CMID;     // WPB*COUT (if CNEXT)

    const int t = threadIdx.x;
    for (int i = t; i < 3 * CMID; i += THREADS) sw1p[i] = w1pos[i];
    for (int i = t; i < CMID * COUT; i += THREADS) sw2[i] = w2[i];
    for (int i = t; i < COUT; i += THREADS) sb2[i] = b2[i];
    __syncthreads();

    const int w = t >> 5, lane = t & 31;
    const int q = qblk * WPB + w;
    const int b = q / Mq;
    const int kcnt = cnt[q];
    const float qx = pos_q[q * 3 + 0];
    const float qy = pos_q[q * 3 + 1];
    const float qz = pos_q[q * 3 + 2];
    float* msg = smsg + w * NB * 3;
    float* h1  = sh1 + w * NB * CMID;
    const int* nb_ptr = nbr + (size_t)q * KNBR;
    const float* xw = xw_src + (size_t)b * NSRC * CMID;
    const float* ps = pos_src + (size_t)b * NSRC * 3;

    float bias2[V2];
#pragma unroll
    for (int r = 0; r < V2; r++) bias2[r] = sb2[V2 * lane + r];

    float vmax[V2];
#pragma unroll
    for (int r = 0; r < V2; r++) vmax[r] = -INFINITY;

    for (int n0 = 0; n0 < kcnt; n0 += NB) {
        const int nv = min(NB, kcnt - n0);
        for (int e = lane; e < NB * 3; e += 32) {
            int nbn = e / 3, d = e - 3 * nbn;
            float v = 0.0f;
            if (nbn < nv) {
                int nid = nb_ptr[n0 + nbn];
                float qc = (d == 0) ? qx : ((d == 1) ? qy : qz);
                v = ps[nid * 3 + d] - qc;
            }
            msg[e] = v;
        }
        __syncwarp();
        float acc[NB][V1];
#pragma unroll
        for (int nbn = 0; nbn < NB; nbn++) {
            if (nbn < nv) {
                int nid = nb_ptr[n0 + nbn];
                vldg<V1>(acc[nbn], xw + (size_t)nid * CMID + V1 * lane);
            } else {
#pragma unroll
                for (int r = 0; r < V1; r++) acc[nbn][r] = 0.0f;
            }
        }
#pragma unroll
        for (int d = 0; d < 3; d++) {
            float wv[V1];
            vldf<V1>(wv, sw1p + d * CMID + V1 * lane);
#pragma unroll
            for (int nbn = 0; nbn < NB; nbn++) {
                float mv = msg[nbn * 3 + d];
#pragma unroll
                for (int r = 0; r < V1; r++)
                    acc[nbn][r] = fmaf(mv, wv[r], acc[nbn][r]);
            }
        }
#pragma unroll
        for (int nbn = 0; nbn < NB; nbn++) {
            float hv[V1];
#pragma unroll
            for (int r = 0; r < V1; r++) hv[r] = fmaxf(acc[nbn][r], 0.0f);
            vstf<V1>(h1 + nbn * CMID + V1 * lane, hv);
        }
        __syncwarp();
        float acc2[NB][V2];
#pragma unroll
        for (int nbn = 0; nbn < NB; nbn++)
#pragma unroll
            for (int r = 0; r < V2; r++) acc2[nbn][r] = bias2[r];
        for (int j = 0; j < CMID; j += 2) {
            float wv0[V2], wv1[V2];
            vldf<V2>(wv0, sw2 + j * COUT + V2 * lane);
            vldf<V2>(wv1, sw2 + (j + 1) * COUT + V2 * lane);
#pragma unroll
            for (int nbn = 0; nbn < NB; nbn++) {
                float2 hp = *(const float2*)(h1 + nbn * CMID + j);
#pragma unroll
                for (int r = 0; r < V2; r++) {
                    acc2[nbn][r] = fmaf(hp.x, wv0[r], acc2[nbn][r]);
                    acc2[nbn][r] = fmaf(hp.y, wv1[r], acc2[nbn][r]);
                }
            }
        }
#pragma unroll
        for (int nbn = 0; nbn < NB; nbn++) {
            if (nbn < nv) {
#pragma unroll
                for (int r = 0; r < V2; r++)
                    vmax[r] = fmaxf(vmax[r], acc2[nbn][r]);
            }
        }
        __syncwarp();
    }
    float ov[V2];
#pragma unroll
    for (int r = 0; r < V2; r++) ov[r] = (kcnt > 0) ? vmax[r] : 0.0f;

    if constexpr (CNEXT == 0) {
        vstf<V2>(dst + (size_t)q * COUT + V2 * lane, ov);
    } else {
#pragma unroll
        for (int r = 0; r < V2; r++) srow[w * COUT + V2 * lane + r] = ov[r];
        __syncwarp();
        const float* row = srow + w * COUT;
#pragma unroll
        for (int o = lane; o < CNEXT; o += 32) {
            float a = __ldg(&bn[o]);
#pragma unroll 8
            for (int c = 0; c < COUT; c++)
                a = fmaf(row[c], __ldg(&wn[c * CNEXT + o]), a);
            dst[(size_t)q * CNEXT + o] = a;
        }
    }
}

static __host__ __device__ constexpr size_t mlpxw_bytes(int CMID, int COUT,
                                                        int NB, int THREADS,
                                                        int CNEXT) {
    int WPB = THREADS / 32;
    return (size_t)(3 * CMID + CMID * COUT + COUT + WPB * NB * 3 +
                    WPB * NB * CMID + (CNEXT > 0 ? WPB * COUT : 0)) * 4;
}

// ------------------------------ pack role ----------------------------------
__device__ __forceinline__ void pack_impl(int rb, const float* __restrict__ p3,
                                          float* __restrict__ out) {
    const int X3  = BB * M3 * 128;
    const int P3S = BB * M3 * 3;
    int i = rb * TPB + threadIdx.x;
    if (i < P3S) out[X3 + i] = p3[i];
    if (i < BB * M3) out[X3 + P3S + i] = (float)(i >> 9);
}

// ------------------------------ kernels ------------------------------------
#define RSQ1 ((float)(0.2 * 0.2))
#define RSQ2 ((float)(0.4 * 0.4))
#define RSQ3 ((float)(1.0 * 1.0))

__global__ void __launch_bounds__(TPB)
fps1_kernel(const float* __restrict__ pos, float* __restrict__ p1) {
    fps_impl<N1, M1, TPB>(pos + (size_t)blockIdx.x * N1 * 3,
                          p1 + (size_t)blockIdx.x * M1 * 3);
}

// fps2 (8 blocks) | ballq1 (BB*M1 blocks)
__global__ void __launch_bounds__(TPB)
combo2_kernel(const float* __restrict__ pos, const float* __restrict__ p1,
              float* __restrict__ p2, int* __restrict__ nbr1, int* __restrict__ cnt1) {
    if (blockIdx.x < BB) {
        fps_impl<M1, M2, TPB>(p1 + (size_t)blockIdx.x * M1 * 3,
                              p2 + (size_t)blockIdx.x * M2 * 3);
    } else {
        ballq_impl<N1, TPB>(blockIdx.x - BB, pos, p1, nbr1, cnt1, RSQ1, M1);
    }
}

// fps3 (8) | mlp1+xw2fuse (BB*M1/8) | ballq2 (BB*M2)
__global__ void __launch_bounds__(TPB)
combo3_kernel(const float* __restrict__ pos, const float* __restrict__ p1,
              const float* __restrict__ p2, float* __restrict__ p3,
              const int* __restrict__ nbr1, const int* __restrict__ cnt1,
              float* __restrict__ xw2, int* __restrict__ nbr2, int* __restrict__ cnt2,
              const float* __restrict__ w11, const float* __restrict__ b11,
              const float* __restrict__ w12, const float* __restrict__ b12,
              const float* __restrict__ w21, const float* __restrict__ b21) {
    const int bid = blockIdx.x;
    if (bid < BB) {
        fps_impl<M2, M3, TPB>(p2 + (size_t)bid * M2 * 3, p3 + (size_t)bid * M3 * 3);
    } else if (bid < BB + BB * M1 / 8) {
        mlp1_impl<8, TPB, 64>(bid - BB, pos, p1, nbr1, cnt1,
                              w11, b11, w12, b12, w21, b21, xw2, N1, M1);
    } else {
        ballq_impl<M1, TPB>(bid - BB - BB * M1 / 8, p1, p2, nbr2, cnt2, RSQ2, M2);
    }
}

// mlp2+xw3fuse (BB*M2/8) | ballq3 (BB*M3) | pack (48)
__global__ void __launch_bounds__(TPB)
combo4_kernel(const float* __restrict__ xw2, const float* __restrict__ p1,
              const float* __restrict__ p2, const float* __restrict__ p3,
              const int* __restrict__ nbr2, const int* __restrict__ cnt2,
              float* __restrict__ xw3, int* __restrict__ nbr3, int* __restrict__ cnt3,
              float* __restrict__ out,
              const float* __restrict__ w21, const float* __restrict__ b21,
              const float* __restrict__ w22, const float* __restrict__ b22,
              const float* __restrict__ w31, const float* __restrict__ b31) {
    const int bid = blockIdx.x;
    constexpr int MLP2B = BB * M2 / 8;
    if (bid < MLP2B) {
        mlpxw_impl<64, 64, 8, TPB, 128>(bid, xw2, p1, p2, nbr2, cnt2,
                                        w21 + 32 * 64, w22, b22, w31, b31,
                                        xw3, M1, M2);
    } else if (bid < MLP2B + BB * M3) {
        ballq_impl<M2, TPB>(bid - MLP2B, p2, p3, nbr3, cnt3, RSQ3, M3);
    } else {
        pack_impl(bid - MLP2B - BB * M3, p3, out);
    }
}

__global__ void __launch_bounds__(TPB)
mlp3_kernel(const float* __restrict__ xw3, const float* __restrict__ p2,
            const float* __restrict__ p3, const int* __restrict__ nbr3,
            const int* __restrict__ cnt3, float* __restrict__ out,
            const float* __restrict__ w31, const float* __restrict__ w32,
            const float* __restrict__ b32) {
    mlpxw_impl<128, 128, 8, TPB, 0>(blockIdx.x, xw3, p2, p3, nbr3, cnt3,
                                    w31 + 64 * 128, w32, b32,
                                    nullptr, nullptr, out, M2, M3);
}

// ------------------------------ host launch --------------------------------
static inline size_t smax(size_t a, size_t b) { return a > b ? a : b; }

extern "C" void kernel_launch(void* const* d_in, const int* in_sizes, int n_in,
                              void* d_out, int out_size) {
    const float* pos = (const float*)d_in[0];
    const float* w11 = (const float*)d_in[2];
    const float* b11 = (const float*)d_in[3];
    const float* w12 = (const float*)d_in[4];
    const float* b12 = (const float*)d_in[5];
    const float* w21 = (const float*)d_in[6];
    const float* b21 = (const float*)d_in[7];
    const float* w22 = (const float*)d_in[8];
    const float* b22 = (const float*)d_in[9];
    const float* w31 = (const float*)d_in[10];
    const float* b31 = (const float*)d_in[11];
    const float* w32 = (const float*)d_in[12];
    const float* b32 = (const float*)d_in[13];
    float* out = (float*)d_out;

    float *p1, *p2, *p3, *xw2, *xw3;
    int *nbr1, *cnt1, *nbr2, *cnt2, *nbr3, *cnt3;
    cudaGetSymbolAddress((void**)&p1, g_p1);
    cudaGetSymbolAddress((void**)&p2, g_p2);
    cudaGetSymbolAddress((void**)&p3, g_p3);
    cudaGetSymbolAddress((void**)&xw2, g_xw2);
    cudaGetSymbolAddress((void**)&xw3, g_xw3);
    cudaGetSymbolAddress((void**)&nbr1, g_nbr1);
    cudaGetSymbolAddress((void**)&cnt1, g_cnt1);
    cudaGetSymbolAddress((void**)&nbr2, g_nbr2);
    cudaGetSymbolAddress((void**)&cnt2, g_cnt2);
    cudaGetSymbolAddress((void**)&nbr3, g_nbr3);
    cudaGetSymbolAddress((void**)&cnt3, g_cnt3);

    const size_t sz1 = fps_bytes(N1, TPB);
    const size_t sz2 = smax(fps_bytes(M1, TPB), ballq_bytes(N1));
    const size_t sz3 = smax(smax(fps_bytes(M2, TPB), mlp1_bytes(8, TPB)),
                            ballq_bytes(M1));
    const size_t sz4 = smax(mlpxw_bytes(64, 64, 8, TPB, 128), ballq_bytes(M2));
    const size_t sz5 = mlpxw_bytes(128, 128, 8, TPB, 0);

    cudaFuncSetAttribute(fps1_kernel, cudaFuncAttributeMaxDynamicSharedMemorySize, (int)sz1);
    cudaFuncSetAttribute(combo2_kernel, cudaFuncAttributeMaxDynamicSharedMemorySize, (int)sz2);
    cudaFuncSetAttribute(combo3_kernel, cudaFuncAttributeMaxDynamicSharedMemorySize, (int)sz3);
    cudaFuncSetAttribute(combo4_kernel, cudaFuncAttributeMaxDynamicSharedMemorySize, (int)sz4);
    cudaFuncSetAttribute(mlp3_kernel, cudaFuncAttributeMaxDynamicSharedMemorySize, (int)sz5);

    fps1_kernel<<<BB, TPB, sz1>>>(pos, p1);
    combo2_kernel<<<BB + BB * M1, TPB, sz2>>>(pos, p1, p2, nbr1, cnt1);
    combo3_kernel<<<BB + BB * M1 / 8 + BB * M2, TPB, sz3>>>(
        pos, p1, p2, p3, nbr1, cnt1, xw2, nbr2, cnt2,
        w11, b11, w12, b12, w21, b21);
    combo4_kernel<<<BB * M2 / 8 + BB * M3 + 48, TPB, sz4>>>(
        xw2, p1, p2, p3, nbr2, cnt2, xw3, nbr3, cnt3, out,
        w21, b21, w22, b22, w31, b31);
    mlp3_kernel<<<BB * M3 / 8, TPB, sz5>>>(
        xw3, p2, p3, nbr3, cnt3, out, w31, w32, b32);
}

// round 14
// speedup vs baseline: 1.1623x; 1.1623x over previous
#include <cuda_runtime.h>
#include <cuda_bf16.h>
#include <math.h>
#include <stdint.h>

// ---------------------------------------------------------------------------
// PointNet++ encoder: 3 SA layers. B=8, N=4096.
// L1: m=2048 r=0.2 (3->32->32). L2: m=512 r=0.4 (32->64->64).
// L3: m=512 r=1.0 (64->128->128). k=64.
// Output = concat(x3 [8,512,128], p3 [8,512,3], batch [8,512]) as f32.
//
// R6 structure (best proven: fps chain + radix ballq + xw-fused MLPs).
// Ballq: byte-3 histogram fused into the distance pass -> radix pass 3 skips
// its zero/count phases and 2 barriers. Bit-exact.
//
// Launch plan:
//   1. fps1 (256 thr)
//   2. combo2: fps2 | ballq1
//   3. combo3: fps3 | mlp1(+fuse xw2) | ballq2
//   4. combo4: mlp2(+fuse xw3) | ballq3 | pack
//   5. mlp3 -> out
// ---------------------------------------------------------------------------

#define BB   8
#define N1   4096
#define M1   2048
#define M2   512
#define M3   512
#define KNBR 64
#define TPB  256

typedef unsigned long long ull;

// ------------------------------ scratch ------------------------------------
__device__ __align__(16) float g_p1[BB * M1 * 3];
__device__ __align__(16) float g_p2[BB * M2 * 3];
__device__ __align__(16) float g_p3[BB * M3 * 3];
__device__ __align__(16) float g_xw2[BB * M1 * 64];    // b21 + x1 @ w21[:32]
__device__ __align__(16) float g_xw3[BB * M2 * 128];   // b31 + x2 @ w31[:64]
__device__ int   g_nbr1[BB * M1 * KNBR];
__device__ int   g_cnt1[BB * M1];
__device__ int   g_nbr2[BB * M2 * KNBR];
__device__ int   g_cnt2[BB * M2];
__device__ int   g_nbr3[BB * M3 * KNBR];
__device__ int   g_cnt3[BB * M3];

// ------------------------------ f32x2 packed helpers ------------------------
__device__ __forceinline__ ull pk2(float lo, float hi) {
    ull r; asm("mov.b64 %0, {%1, %2};" : "=l"(r) : "f"(lo), "f"(hi)); return r;
}
__device__ __forceinline__ void upk2(float& lo, float& hi, ull v) {
    asm("mov.b64 {%0, %1}, %2;" : "=f"(lo), "=f"(hi) : "l"(v));
}
__device__ __forceinline__ ull add2(ull a, ull b) {
    ull d; asm("add.rn.f32x2 %0, %1, %2;" : "=l"(d) : "l"(a), "l"(b)); return d;
}
__device__ __forceinline__ ull mul2(ull a, ull b) {
    ull d; asm("mul.rn.f32x2 %0, %1, %2;" : "=l"(d) : "l"(a), "l"(b)); return d;
}
__device__ __forceinline__ ull fma2(ull a, ull b, ull c) {
    ull d; asm("fma.rn.f32x2 %0, %1, %2, %3;" : "=l"(d) : "l"(a), "l"(b), "l"(c)); return d;
}

// ------------------------------ FPS (exact R6) -------------------------------
// Packed f32x2 distance update (bit-exact). Fused value+index argmax tree
// (ge keeps lower index on ties). One __syncthreads per step.
template <int N, int M, int THREADS>
__device__ __forceinline__ void fps_impl(const float* __restrict__ pb,
                                         float* __restrict__ po) {
    constexpr int P  = N / THREADS;
    constexpr int H  = P / 2;
    constexpr int NW = THREADS / 32;
    extern __shared__ char smraw[];
    float*    sx = (float*)smraw;
    float*    sy = sx + N;
    float*    sz = sy + N;
    unsigned* kb = (unsigned*)(sz + N);   // [2][NW]
    int*      ib = (int*)(kb + 2 * NW);   // [2][NW]

    const int t = threadIdx.x;
    const int lane = t & 31, wid = t >> 5;

    for (int i = t; i < N; i += THREADS) {
        sx[i] = pb[3 * i + 0];
        sy[i] = pb[3 * i + 1];
        sz[i] = pb[3 * i + 2];
    }
    __syncthreads();

    ull rxp[H], ryp[H], rzp[H];
    float md[P];
    int idx0[P];
#pragma unroll
    for (int j = 0; j < P; j++) idx0[j] = t + j * THREADS;
    const float x0 = sx[0], y0 = sy[0], z0 = sz[0];
    {
        const ull ncx = pk2(-x0, -x0), ncy = pk2(-y0, -y0), ncz = pk2(-z0, -z0);
#pragma unroll
        for (int h = 0; h < H; h++) {
            int i0 = t + (2 * h) * THREADS, i1 = t + (2 * h + 1) * THREADS;
            rxp[h] = pk2(sx[i0], sx[i1]);
            ryp[h] = pk2(sy[i0], sy[i1]);
            rzp[h] = pk2(sz[i0], sz[i1]);
            ull dx = add2(rxp[h], ncx);
            ull dy = add2(ryp[h], ncy);
            ull dz = add2(rzp[h], ncz);
            ull d2 = fma2(dz, dz, fma2(dy, dy, mul2(dx, dx)));
            upk2(md[2 * h], md[2 * h + 1], d2);
        }
    }
    if (t == 0) { po[0] = x0; po[1] = y0; po[2] = z0; }

    for (int s = 1; s < M; s++) {
        float tv[P]; int ti0[P];
#pragma unroll
        for (int j = 0; j < P; j++) { tv[j] = md[j]; ti0[j] = idx0[j]; }
#pragma unroll
        for (int st = 1; st < P; st <<= 1)
#pragma unroll
            for (int j = 0; j + st < P; j += 2 * st) {
                bool ge = tv[j] >= tv[j + st];
                tv[j]  = fmaxf(tv[j], tv[j + st]);
                ti0[j] = ge ? ti0[j] : ti0[j + st];
            }
        const float bv = tv[0];
        const int   bi = ti0[0];
        unsigned key  = __float_as_uint(bv);
        unsigned wmax = __reduce_max_sync(0xffffffffu, key);
        int wbi = __reduce_min_sync(0xffffffffu,
                                    (key == wmax) ? bi : 0x7fffffff);
        const int par = (s & 1) * NW;
        if (lane == 0) { kb[par + wid] = wmax; ib[par + wid] = wbi; }
        __syncthreads();
        unsigned kv[NW]; int iv[NW];
#pragma unroll
        for (int w2 = 0; w2 < NW; w2++) { kv[w2] = kb[par + w2]; iv[w2] = ib[par + w2]; }
#pragma unroll
        for (int st = 1; st < NW; st <<= 1)
#pragma unroll
            for (int w2 = 0; w2 + st < NW; w2 += 2 * st) {
                unsigned ka = kv[w2], kc = kv[w2 + st];
                int ia = iv[w2], ic = iv[w2 + st];
                int imin = min(ia, ic);
                iv[w2] = (ka > kc) ? ia : ((ka < kc) ? ic : imin);
                kv[w2] = (ka > kc) ? ka : kc;
            }
        const int bx = iv[0];

        const float cx = sx[bx], cy = sy[bx], cz = sz[bx];
        if (t == 0) { po[3 * s] = cx; po[3 * s + 1] = cy; po[3 * s + 2] = cz; }
        const ull ncx = pk2(-cx, -cx), ncy = pk2(-cy, -cy), ncz = pk2(-cz, -cz);
#pragma unroll
        for (int h = 0; h < H; h++) {
            ull dx = add2(rxp[h], ncx);
            ull dy = add2(ryp[h], ncy);
            ull dz = add2(rzp[h], ncz);
            ull d2 = fma2(dz, dz, fma2(dy, dy, mul2(dx, dx)));
            float d0, d1; upk2(d0, d1, d2);
            md[2 * h]     = fminf(md[2 * h], d0);
            md[2 * h + 1] = fminf(md[2 * h + 1], d1);
        }
    }
}

static __host__ __device__ constexpr size_t fps_bytes(int N, int THREADS) {
    return (size_t)(3 * N) * 4 + 2 * (THREADS / 32) * 8;
}

// ------------------------------ radix scan helper ---------------------------
// Warp 0 scans the 256-bin histogram and selects the bin containing the
// `need`-th smallest element; writes new prefix/need into s_scal[1]/[2].
__device__ __forceinline__ void radix_scan(int t, const int* __restrict__ hist,
                                           int* __restrict__ s_scal,
                                           int need, unsigned prefix, int sh) {
    if (t < 32) {
        int loc[8], ssum = 0;
#pragma unroll
        for (int j = 0; j < 8; j++) { loc[j] = hist[t * 8 + j]; ssum += loc[j]; }
        int inc = ssum;
#pragma unroll
        for (int off = 1; off < 32; off <<= 1) {
            int n = __shfl_up_sync(0xffffffffu, inc, off);
            if (t >= off) inc += n;
        }
        int excl = inc - ssum;
        if (need > excl && need <= inc) {   // exactly one lane
            int cum = excl;
#pragma unroll
            for (int j = 0; j < 8; j++) {
                cum += loc[j];
                if (need <= cum) {
                    s_scal[1] = (int)(prefix | ((unsigned)(t * 8 + j) << sh));
                    s_scal[2] = need - (cum - loc[j]);
                    break;
                }
            }
        }
    }
}

// ------------------------------ ball query ---------------------------------
// Compact in-radius candidates; the byte-3 histogram is built during the
// distance pass (key already in-register), so radix pass 3 skips its zero +
// count phases. Then select the 64 smallest keys (ties -> smallest index).
// Output order arbitrary (max-aggregation downstream is order-free).
template <int NSRC, int THREADS>
__device__ __forceinline__ void ballq_impl(int q, const float* __restrict__ pos_src,
                                           const float* __restrict__ pos_q,
                                           int* __restrict__ nbr, int* __restrict__ cnt,
                                           float rsq, int Mq) {
    extern __shared__ char smraw[];
    unsigned* s_keys = (unsigned*)smraw;
    int* s_idx  = (int*)(s_keys + NSRC);
    int* hist   = s_idx + NSRC;          // 256
    int* s_scal = hist + 256;            // [0]=counter [1]=prefix [2]=need [3]=outcnt

    const int b = q / Mq;
    const int t = threadIdx.x;
    if (t == 0) { s_scal[0] = 0; s_scal[3] = 0; }
    for (int i = t; i < 256; i += THREADS) hist[i] = 0;
    __syncthreads();

    const float qx = pos_q[q * 3 + 0];
    const float qy = pos_q[q * 3 + 1];
    const float qz = pos_q[q * 3 + 2];
    const float qn = fmaf(qz, qz, fmaf(qy, qy, qx * qx));
    const float* ps = pos_src + (size_t)b * NSRC * 3;

    for (int i = t; i < NSRC; i += THREADS) {
        float sxx = ps[i * 3 + 0], syy = ps[i * 3 + 1], szz = ps[i * 3 + 2];
        float sn  = fmaf(szz, szz, fmaf(syy, syy, sxx * sxx));
        float dot = fmaf(qz, szz, fmaf(qy, syy, qx * sxx));
        float d2  = fmaf(-2.0f, dot, qn + sn);
        if (d2 <= rsq) {
            int p = atomicAdd(&s_scal[0], 1);
            unsigned u = __float_as_uint(d2);
            u = ((int)u >= 0) ? (u ^ 0x80000000u) : ~u;   // monotone f32->u32
            s_keys[p] = u;
            s_idx[p]  = i;
            atomicAdd(&hist[u >> 24], 1);                 // fused byte-3 hist
        }
    }
    __syncthreads();
    const int c = s_scal[0];
    int* onbr = nbr + (size_t)q * KNBR;

    if (c <= KNBR) {
        for (int e = t; e < c; e += THREADS) onbr[e] = s_idx[e];
        if (t == 0) cnt[q] = c;
        return;
    }

    // ---- pass for byte 3: histogram already built during distance pass ----
    radix_scan(t, hist, s_scal, KNBR, 0u, 24);
    __syncthreads();
    unsigned prefix = (unsigned)s_scal[1];
    int need = s_scal[2];

    // ---- passes for bytes 2..0 ----
#pragma unroll
    for (int byte = 2; byte >= 0; byte--) {
        for (int i = t; i < 256; i += THREADS) hist[i] = 0;
        __syncthreads();
        const int sh = byte * 8;
        const unsigned himask = 0xFFFFFFFFu << (sh + 8);
        for (int e = t; e < c; e += THREADS) {
            unsigned k = s_keys[e];
            if ((k & himask) == prefix) atomicAdd(&hist[(k >> sh) & 255], 1);
        }
        __syncthreads();
        radix_scan(t, hist, s_scal, need, prefix, sh);
        __syncthreads();
        prefix = (unsigned)s_scal[1];
        need   = s_scal[2];
    }

    // prefix == T (64th smallest); keys < T all pass; among keys == T take
    // the `need` smallest-index elements.
    for (int e = t; e < c; e += THREADS) {
        unsigned k = s_keys[e];
        if (k < prefix) {
            int p = atomicAdd(&s_scal[3], 1);
            onbr[p] = s_idx[e];
        } else if (k == prefix) {
            int my = s_idx[e];
            int r = 0;
            for (int j = 0; j < c; j++)
                r += (s_keys[j] == prefix) && (s_idx[j] < my);
            if (r < need) onbr[KNBR - need + r] = my;
        }
    }
    if (t == 0) cnt[q] = KNBR;
}

static __host__ __device__ constexpr size_t ballq_bytes(int NSRC) {
    return (size_t)NSRC * 8 + 256 * 4 + 16;
}

// ------------------------------ MLP helpers ---------------------------------
template <int V>
__device__ __forceinline__ void vldf(float* d, const float* s) {
    if constexpr (V == 4) { float4 v = *(const float4*)s; d[0]=v.x; d[1]=v.y; d[2]=v.z; d[3]=v.w; }
    else if constexpr (V == 2) { float2 v = *(const float2*)s; d[0]=v.x; d[1]=v.y; }
    else { d[0] = s[0]; }
}
template <int V>
__device__ __forceinline__ void vstf(float* d, const float* s) {
    if constexpr (V == 4) { *(float4*)d = make_float4(s[0], s[1], s[2], s[3]); }
    else if constexpr (V == 2) { *(float2*)d = make_float2(s[0], s[1]); }
    else { d[0] = s[0]; }
}
template <int V>
__device__ __forceinline__ void vldg(float* d, const float* s) {
    if constexpr (V == 4) { float4 v = __ldg((const float4*)s); d[0]=v.x; d[1]=v.y; d[2]=v.z; d[3]=v.w; }
    else if constexpr (V == 2) { float2 v = __ldg((const float2*)s); d[0]=v.x; d[1]=v.y; }
    else { d[0] = __ldg(s); }
}

// ------------------------------ MLP layer 1 (msg-based) + fuse xw2 ----------
template <int NB, int THREADS, int CNEXT>
__device__ __forceinline__ void mlp1_impl(int qblk,
        const float* __restrict__ pos_src, const float* __restrict__ pos_q,
        const int* __restrict__ nbr, const int* __restrict__ cnt,
        const float* __restrict__ w1, const float* __restrict__ b1,
        const float* __restrict__ w2, const float* __restrict__ b2,
        const float* __restrict__ wn, const float* __restrict__ bn,
        float* __restrict__ xw_out, int NSRC, int Mq) {
    constexpr int CMID = 32, COUT = 32, MSG = 6;
    constexpr int WPB = THREADS / 32;

    extern __shared__ char smraw[];
    float* sw1  = (float*)smraw;             // 6*32
    float* sb1  = sw1 + MSG * CMID;          // 32
    float* sw2  = sb1 + CMID;                // 32*32
    float* sb2  = sw2 + CMID * COUT;         // 32
    float* smsg = sb2 + COUT;                // WPB*NB*6
    float* sh1  = smsg + WPB * NB * MSG;     // WPB*NB*32
    float* srow = sh1 + WPB * NB * CMID;     // WPB*32

    const int t = threadIdx.x;
    for (int i = t; i < MSG * CMID; i += THREADS) sw1[i] = w1[i];
    for (int i = t; i < CMID; i += THREADS) sb1[i] = b1[i];
    for (int i = t; i < CMID * COUT; i += THREADS) sw2[i] = w2[i];
    for (int i = t; i < COUT; i += THREADS) sb2[i] = b2[i];
    __syncthreads();

    const int w = t >> 5, lane = t & 31;
    const int q = qblk * WPB + w;
    const int b = q / Mq;
    const int kcnt = cnt[q];
    const float qx = pos_q[q * 3 + 0];
    const float qy = pos_q[q * 3 + 1];
    const float qz = pos_q[q * 3 + 2];
    float* msg = smsg + w * NB * MSG;
    float* h1  = sh1 + w * NB * CMID;
    const int* nb_ptr = nbr + (size_t)q * KNBR;
    const float* ps = pos_src + (size_t)b * NSRC * 3;

    const float bias1 = sb1[lane];
    const float bias2 = sb2[lane];
    float vmax = -INFINITY;

    for (int n0 = 0; n0 < kcnt; n0 += NB) {
        const int nv = min(NB, kcnt - n0);
        for (int e = lane; e < NB * MSG; e += 32) {
            int nbn = e / MSG, i = e - nbn * MSG;
            float v = 0.0f;
            if (nbn < nv) {
                int nid = nb_ptr[n0 + nbn];
                if (i < 3) {
                    v = ps[nid * 3 + i];
                } else {
                    float qc = (i == 3) ? qx : ((i == 4) ? qy : qz);
                    v = ps[nid * 3 + (i - 3)] - qc;
                }
            }
            msg[e] = v;
        }
        __syncwarp();
        float acc[NB];
#pragma unroll
        for (int nbn = 0; nbn < NB; nbn++) acc[nbn] = bias1;
#pragma unroll
        for (int i = 0; i < MSG; i++) {
            float wv = sw1[i * CMID + lane];
#pragma unroll
            for (int nbn = 0; nbn < NB; nbn++)
                acc[nbn] = fmaf(msg[nbn * MSG + i], wv, acc[nbn]);
        }
#pragma unroll
        for (int nbn = 0; nbn < NB; nbn++)
            h1[nbn * CMID + lane] = fmaxf(acc[nbn], 0.0f);
        __syncwarp();
        float acc2[NB];
#pragma unroll
        for (int nbn = 0; nbn < NB; nbn++) acc2[nbn] = bias2;
        for (int j = 0; j < CMID; j += 2) {
            float wv0 = sw2[j * COUT + lane];
            float wv1 = sw2[(j + 1) * COUT + lane];
#pragma unroll
            for (int nbn = 0; nbn < NB; nbn++) {
                float2 hp = *(const float2*)(h1 + nbn * CMID + j);
                acc2[nbn] = fmaf(hp.x, wv0, acc2[nbn]);
                acc2[nbn] = fmaf(hp.y, wv1, acc2[nbn]);
            }
        }
#pragma unroll
        for (int nbn = 0; nbn < NB; nbn++)
            if (nbn < nv) vmax = fmaxf(vmax, acc2[nbn]);
        __syncwarp();
    }
    const float ov = (kcnt > 0) ? vmax : 0.0f;
    srow[w * COUT + lane] = ov;
    __syncwarp();
    const float* row = srow + w * COUT;
#pragma unroll
    for (int o = lane; o < CNEXT; o += 32) {
        float a = __ldg(&bn[o]);
#pragma unroll 8
        for (int c = 0; c < COUT; c++)
            a = fmaf(row[c], __ldg(&wn[c * CNEXT + o]), a);
        xw_out[(size_t)q * CNEXT + o] = a;
    }
}

static __host__ __device__ constexpr size_t mlp1_bytes(int NB, int THREADS) {
    int WPB = THREADS / 32;
    return (size_t)(6 * 32 + 32 + 32 * 32 + 32 + WPB * NB * 6 +
                    WPB * NB * 32 + WPB * 32) * 4;
}

// ------------------------------ MLP layers 2/3 (xw-based) -------------------
template <int CMID, int COUT, int NB, int THREADS, int CNEXT>
__device__ __forceinline__ void mlpxw_impl(int qblk,
        const float* __restrict__ xw_src, const float* __restrict__ pos_src,
        const float* __restrict__ pos_q, const int* __restrict__ nbr,
        const int* __restrict__ cnt,
        const float* __restrict__ w1pos,      // [3][CMID]
        const float* __restrict__ w2, const float* __restrict__ b2,
        const float* __restrict__ wn, const float* __restrict__ bn,
        float* __restrict__ dst, int NSRC, int Mq) {
    constexpr int V1  = CMID / 32;
    constexpr int V2  = COUT / 32;
    constexpr int WPB = THREADS / 32;

    extern __shared__ char smraw[];
    float* sw1p = (float*)smraw;             // 3*CMID
    float* sw2  = sw1p + 3 * CMID;           // CMID*COUT
    float* sb2  = sw2 + CMID * COUT;         // COUT
    float* smsg = sb2 + COUT;                // WPB*NB*3
    float* sh1  = smsg + WPB * NB * 3;       // WPB*NB*CMID
    float* srow = sh1 + WPB * NB * CMID;     // WPB*COUT (if CNEXT)

    const int t = threadIdx.x;
    for (int i = t; i < 3 * CMID; i += THREADS) sw1p[i] = w1pos[i];
    for (int i = t; i < CMID * COUT; i += THREADS) sw2[i] = w2[i];
    for (int i = t; i < COUT; i += THREADS) sb2[i] = b2[i];
    __syncthreads();

    const int w = t >> 5, lane = t & 31;
    const int q = qblk * WPB + w;
    const int b = q / Mq;
    const int kcnt = cnt[q];
    const float qx = pos_q[q * 3 + 0];
    const float qy = pos_q[q * 3 + 1];
    const float qz = pos_q[q * 3 + 2];
    float* msg = smsg + w * NB * 3;
    float* h1  = sh1 + w * NB * CMID;
    const int* nb_ptr = nbr + (size_t)q * KNBR;
    const float* xw = xw_src + (size_t)b * NSRC * CMID;
    const float* ps = pos_src + (size_t)b * NSRC * 3;

    float bias2[V2];
#pragma unroll
    for (int r = 0; r < V2; r++) bias2[r] = sb2[V2 * lane + r];

    float vmax[V2];
#pragma unroll
    for (int r = 0; r < V2; r++) vmax[r] = -INFINITY;

    for (int n0 = 0; n0 < kcnt; n0 += NB) {
        const int nv = min(NB, kcnt - n0);
        for (int e = lane; e < NB * 3; e += 32) {
            int nbn = e / 3, d = e - 3 * nbn;
            float v = 0.0f;
            if (nbn < nv) {
                int nid = nb_ptr[n0 + nbn];
                float qc = (d == 0) ? qx : ((d == 1) ? qy : qz);
                v = ps[nid * 3 + d] - qc;
            }
            msg[e] = v;
        }
        __syncwarp();
        float acc[NB][V1];
#pragma unroll
        for (int nbn = 0; nbn < NB; nbn++) {
            if (nbn < nv) {
                int nid = nb_ptr[n0 + nbn];
                vldg<V1>(acc[nbn], xw + (size_t)nid * CMID + V1 * lane);
            } else {
#pragma unroll
                for (int r = 0; r < V1; r++) acc[nbn][r] = 0.0f;
            }
        }
#pragma unroll
        for (int d = 0; d < 3; d++) {
            float wv[V1];
            vldf<V1>(wv, sw1p + d * CMID + V1 * lane);
#pragma unroll
            for (int nbn = 0; nbn < NB; nbn++) {
                float mv = msg[nbn * 3 + d];
#pragma unroll
                for (int r = 0; r < V1; r++)
                    acc[nbn][r] = fmaf(mv, wv[r], acc[nbn][r]);
            }
        }
#pragma unroll
        for (int nbn = 0; nbn < NB; nbn++) {
            float hv[V1];
#pragma unroll
            for (int r = 0; r < V1; r++) hv[r] = fmaxf(acc[nbn][r], 0.0f);
            vstf<V1>(h1 + nbn * CMID + V1 * lane, hv);
        }
        __syncwarp();
        float acc2[NB][V2];
#pragma unroll
        for (int nbn = 0; nbn < NB; nbn++)
#pragma unroll
            for (int r = 0; r < V2; r++) acc2[nbn][r] = bias2[r];
        for (int j = 0; j < CMID; j += 2) {
            float wv0[V2], wv1[V2];
            vldf<V2>(wv0, sw2 + j * COUT + V2 * lane);
            vldf<V2>(wv1, sw2 + (j + 1) * COUT + V2 * lane);
#pragma unroll
            for (int nbn = 0; nbn < NB; nbn++) {
                float2 hp = *(const float2*)(h1 + nbn * CMID + j);
#pragma unroll
                for (int r = 0; r < V2; r++) {
                    acc2[nbn][r] = fmaf(hp.x, wv0[r], acc2[nbn][r]);
                    acc2[nbn][r] = fmaf(hp.y, wv1[r], acc2[nbn][r]);
                }
            }
        }
#pragma unroll
        for (int nbn = 0; nbn < NB; nbn++) {
            if (nbn < nv) {
#pragma unroll
                for (int r = 0; r < V2; r++)
                    vmax[r] = fmaxf(vmax[r], acc2[nbn][r]);
            }
        }
        __syncwarp();
    }
    float ov[V2];
#pragma unroll
    for (int r = 0; r < V2; r++) ov[r] = (kcnt > 0) ? vmax[r] : 0.0f;

    if constexpr (CNEXT == 0) {
        vstf<V2>(dst + (size_t)q * COUT + V2 * lane, ov);
    } else {
#pragma unroll
        for (int r = 0; r < V2; r++) srow[w * COUT + V2 * lane + r] = ov[r];
        __syncwarp();
        const float* row = srow + w * COUT;
#pragma unroll
        for (int o = lane; o < CNEXT; o += 32) {
            float a = __ldg(&bn[o]);
#pragma unroll 8
            for (int c = 0; c < COUT; c++)
                a = fmaf(row[c], __ldg(&wn[c * CNEXT + o]), a);
            dst[(size_t)q * CNEXT + o] = a;
        }
    }
}

static __host__ __device__ constexpr size_t mlpxw_bytes(int CMID, int COUT,
                                                        int NB, int THREADS,
                                                        int CNEXT) {
    int WPB = THREADS / 32;
    return (size_t)(3 * CMID + CMID * COUT + COUT + WPB * NB * 3 +
                    WPB * NB * CMID + (CNEXT > 0 ? WPB * COUT : 0)) * 4;
}

// ------------------------------ pack role ----------------------------------
__device__ __forceinline__ void pack_impl(int rb, const float* __restrict__ p3,
                                          float* __restrict__ out) {
    const int X3  = BB * M3 * 128;
    const int P3S = BB * M3 * 3;
    int i = rb * TPB + threadIdx.x;
    if (i < P3S) out[X3 + i] = p3[i];
    if (i < BB * M3) out[X3 + P3S + i] = (float)(i >> 9);
}

// ------------------------------ kernels ------------------------------------
#define RSQ1 ((float)(0.2 * 0.2))
#define RSQ2 ((float)(0.4 * 0.4))
#define RSQ3 ((float)(1.0 * 1.0))

__global__ void __launch_bounds__(TPB)
fps1_kernel(const float* __restrict__ pos, float* __restrict__ p1) {
    fps_impl<N1, M1, TPB>(pos + (size_t)blockIdx.x * N1 * 3,
                          p1 + (size_t)blockIdx.x * M1 * 3);
}

// fps2 (8 blocks) | ballq1 (BB*M1 blocks)
__global__ void __launch_bounds__(TPB)
combo2_kernel(const float* __restrict__ pos, const float* __restrict__ p1,
              float* __restrict__ p2, int* __restrict__ nbr1, int* __restrict__ cnt1) {
    if (blockIdx.x < BB) {
        fps_impl<M1, M2, TPB>(p1 + (size_t)blockIdx.x * M1 * 3,
                              p2 + (size_t)blockIdx.x * M2 * 3);
    } else {
        ballq_impl<N1, TPB>(blockIdx.x - BB, pos, p1, nbr1, cnt1, RSQ1, M1);
    }
}

// fps3 (8) | mlp1+xw2fuse (BB*M1/8) | ballq2 (BB*M2)
__global__ void __launch_bounds__(TPB)
combo3_kernel(const float* __restrict__ pos, const float* __restrict__ p1,
              const float* __restrict__ p2, float* __restrict__ p3,
              const int* __restrict__ nbr1, const int* __restrict__ cnt1,
              float* __restrict__ xw2, int* __restrict__ nbr2, int* __restrict__ cnt2,
              const float* __restrict__ w11, const float* __restrict__ b11,
              const float* __restrict__ w12, const float* __restrict__ b12,
              const float* __restrict__ w21, const float* __restrict__ b21) {
    const int bid = blockIdx.x;
    if (bid < BB) {
        fps_impl<M2, M3, TPB>(p2 + (size_t)bid * M2 * 3, p3 + (size_t)bid * M3 * 3);
    } else if (bid < BB + BB * M1 / 8) {
        mlp1_impl<8, TPB, 64>(bid - BB, pos, p1, nbr1, cnt1,
                              w11, b11, w12, b12, w21, b21, xw2, N1, M1);
    } else {
        ballq_impl<M1, TPB>(bid - BB - BB * M1 / 8, p1, p2, nbr2, cnt2, RSQ2, M2);
    }
}

// mlp2+xw3fuse (BB*M2/8) | ballq3 (BB*M3) | pack (48)
__global__ void __launch_bounds__(TPB)
combo4_kernel(const float* __restrict__ xw2, const float* __restrict__ p1,
              const float* __restrict__ p2, const float* __restrict__ p3,
              const int* __restrict__ nbr2, const int* __restrict__ cnt2,
              float* __restrict__ xw3, int* __restrict__ nbr3, int* __restrict__ cnt3,
              float* __restrict__ out,
              const float* __restrict__ w21, const float* __restrict__ b21,
              const float* __restrict__ w22, const float* __restrict__ b22,
              const float* __restrict__ w31, const float* __restrict__ b31) {
    const int bid = blockIdx.x;
    constexpr int MLP2B = BB * M2 / 8;
    if (bid < MLP2B) {
        mlpxw_impl<64, 64, 8, TPB, 128>(bid, xw2, p1, p2, nbr2, cnt2,
                                        w21 + 32 * 64, w22, b22, w31, b31,
                                        xw3, M1, M2);
    } else if (bid < MLP2B + BB * M3) {
        ballq_impl<M2, TPB>(bid - MLP2B, p2, p3, nbr3, cnt3, RSQ3, M3);
    } else {
        pack_impl(bid - MLP2B - BB * M3, p3, out);
    }
}

__global__ void __launch_bounds__(TPB)
mlp3_kernel(const float* __restrict__ xw3, const float* __restrict__ p2,
            const float* __restrict__ p3, const int* __restrict__ nbr3,
            const int* __restrict__ cnt3, float* __restrict__ out,
            const float* __restrict__ w31, const float* __restrict__ w32,
            const float* __restrict__ b32) {
    mlpxw_impl<128, 128, 8, TPB, 0>(blockIdx.x, xw3, p2, p3, nbr3, cnt3,
                                    w31 + 64 * 128, w32, b32,
                                    nullptr, nullptr, out, M2, M3);
}

// ------------------------------ host launch --------------------------------
static inline size_t smax(size_t a, size_t b) { return a > b ? a : b; }

extern "C" void kernel_launch(void* const* d_in, const int* in_sizes, int n_in,
                              void* d_out, int out_size) {
    const float* pos = (const float*)d_in[0];
    const float* w11 = (const float*)d_in[2];
    const float* b11 = (const float*)d_in[3];
    const float* w12 = (const float*)d_in[4];
    const float* b12 = (const float*)d_in[5];
    const float* w21 = (const float*)d_in[6];
    const float* b21 = (const float*)d_in[7];
    const float* w22 = (const float*)d_in[8];
    const float* b22 = (const float*)d_in[9];
    const float* w31 = (const float*)d_in[10];
    const float* b31 = (const float*)d_in[11];
    const float* w32 = (const float*)d_in[12];
    const float* b32 = (const float*)d_in[13];
    float* out = (float*)d_out;

    float *p1, *p2, *p3, *xw2, *xw3;
    int *nbr1, *cnt1, *nbr2, *cnt2, *nbr3, *cnt3;
    cudaGetSymbolAddress((void**)&p1, g_p1);
    cudaGetSymbolAddress((void**)&p2, g_p2);
    cudaGetSymbolAddress((void**)&p3, g_p3);
    cudaGetSymbolAddress((void**)&xw2, g_xw2);
    cudaGetSymbolAddress((void**)&xw3, g_xw3);
    cudaGetSymbolAddress((void**)&nbr1, g_nbr1);
    cudaGetSymbolAddress((void**)&cnt1, g_cnt1);
    cudaGetSymbolAddress((void**)&nbr2, g_nbr2);
    cudaGetSymbolAddress((void**)&cnt2, g_cnt2);
    cudaGetSymbolAddress((void**)&nbr3, g_nbr3);
    cudaGetSymbolAddress((void**)&cnt3, g_cnt3);

    const size_t sz1 = fps_bytes(N1, TPB);
    const size_t sz2 = smax(fps_bytes(M1, TPB), ballq_bytes(N1));
    const size_t sz3 = smax(smax(fps_bytes(M2, TPB), mlp1_bytes(8, TPB)),
                            ballq_bytes(M1));
    const size_t sz4 = smax(mlpxw_bytes(64, 64, 8, TPB, 128), ballq_bytes(M2));
    const size_t sz5 = mlpxw_bytes(128, 128, 8, TPB, 0);

    cudaFuncSetAttribute(fps1_kernel, cudaFuncAttributeMaxDynamicSharedMemorySize, (int)sz1);
    cudaFuncSetAttribute(combo2_kernel, cudaFuncAttributeMaxDynamicSharedMemorySize, (int)sz2);
    cudaFuncSetAttribute(combo3_kernel, cudaFuncAttributeMaxDynamicSharedMemorySize, (int)sz3);
    cudaFuncSetAttribute(combo4_kernel, cudaFuncAttributeMaxDynamicSharedMemorySize, (int)sz4);
    cudaFuncSetAttribute(mlp3_kernel, cudaFuncAttributeMaxDynamicSharedMemorySize, (int)sz5);

    fps1_kernel<<<BB, TPB, sz1>>>(pos, p1);
    combo2_kernel<<<BB + BB * M1, TPB, sz2>>>(pos, p1, p2, nbr1, cnt1);
    combo3_kernel<<<BB + BB * M1 / 8 + BB * M2, TPB, sz3>>>(
        pos, p1, p2, p3, nbr1, cnt1, xw2, nbr2, cnt2,
        w11, b11, w12, b12, w21, b21);
    combo4_kernel<<<BB * M2 / 8 + BB * M3 + 48, TPB, sz4>>>(
        xw2, p1, p2, p3, nbr2, cnt2, xw3, nbr3, cnt3, out,
        w21, b21, w22, b22, w31, b31);
    mlp3_kernel<<<BB * M3 / 8, TPB, sz5>>>(
        xw3, p2, p3, nbr3, cnt3, out, w31, w32, b32);
}